// round 11
// baseline (speedup 1.0000x reference)
#include <cuda_runtime.h>
#include <cuda_fp16.h>
#include <cstdint>
#include <math.h>

typedef __half hf;

#define Bb 4
#define Lq 1024
#define Dd 1024
#define Hh 8
#define Pp 1024
#define Ff 4096
#define DKc 128

#define SQKV ((long)Bb*Hh*Lq*DKc)

// ---------------- scratch ----------------
__device__ hf g_xn[Bb*Lq*Dd];
__device__ hf g_qkv[3*Bb*Hh*Lq*DKc];      // q | k | v, each [B,H,L,DK]
__device__ hf g_h [Bb*Lq*Ff];
__device__ hf g_w4t[4*Dd*Dd];             // wq^T | wk^T | wv^T | wo^T
__device__ hf g_w1t[Dd*Ff], g_w2t[Dd*Ff];
__device__ hf g_rk [Bb*Hh*Pp*DKc];
__device__ hf g_rv [Bb*Hh*Pp*DKc];
__device__ float g_x[Bb*Lq*Dd];

// ---------------- helpers ----------------
__device__ __forceinline__ void ldsm4(uint32_t r[4], const hf* p){
  uint32_t a = (uint32_t)__cvta_generic_to_shared(p);
  asm volatile("ldmatrix.sync.aligned.m8n8.x4.shared.b16 {%0,%1,%2,%3},[%4];"
    :"=r"(r[0]),"=r"(r[1]),"=r"(r[2]),"=r"(r[3]):"r"(a));
}
__device__ __forceinline__ void ldsm4t(uint32_t r[4], const hf* p){
  uint32_t a = (uint32_t)__cvta_generic_to_shared(p);
  asm volatile("ldmatrix.sync.aligned.m8n8.x4.trans.shared.b16 {%0,%1,%2,%3},[%4];"
    :"=r"(r[0]),"=r"(r[1]),"=r"(r[2]),"=r"(r[3]):"r"(a));
}
__device__ __forceinline__ void mma_f16(float c[4], const uint32_t a[4], const uint32_t b[2]){
  asm volatile("mma.sync.aligned.m16n8k16.row.col.f32.f16.f16.f32 "
    "{%0,%1,%2,%3},{%4,%5,%6,%7},{%8,%9},{%0,%1,%2,%3};"
    :"+f"(c[0]),"+f"(c[1]),"+f"(c[2]),"+f"(c[3])
    :"r"(a[0]),"r"(a[1]),"r"(a[2]),"r"(a[3]),"r"(b[0]),"r"(b[1]));
}
__device__ __forceinline__ void cpa16(hf* dst, const hf* src){
  uint32_t d = (uint32_t)__cvta_generic_to_shared(dst);
  asm volatile("cp.async.cg.shared.global [%0],[%1],16;"::"r"(d),"l"(src));
}
__device__ __forceinline__ void cpa_commit(){ asm volatile("cp.async.commit_group;"); }
template<int N> __device__ __forceinline__ void cpa_wait(){ asm volatile("cp.async.wait_group %0;"::"n"(N)); }

__device__ __forceinline__ float gelu_f(float u){
  return 0.5f*u*(1.f + tanhf(0.7978845608028654f*(u + 0.044715f*u*u*u)));
}
__device__ __forceinline__ uint32_t packh2(float a, float b){
  __half2 h; h.x = __float2half_rn(a); h.y = __float2half_rn(b);
  return *(uint32_t*)&h;
}

// ---------------- dense fp16 GEMM (validated R7/R8 core) ----------------
#define M_QKV   2
#define M_GELU  3
#define M_RES   4

#define PITCH 40
#define PLANE (128*PITCH)

template<int MODE>
__global__ __launch_bounds__(256)
void hgemm(const hf* __restrict__ A, const hf* __restrict__ Bm,
           const float* __restrict__ bias, const float* __restrict__ bias2,
           const float* __restrict__ bias3,
           const float* __restrict__ res,
           float* __restrict__ Cf, hf* __restrict__ Ch,
           int N, int K)
{
  __shared__ hf As[2][PLANE];
  __shared__ hf Bs[2][PLANE];
  int tid = threadIdx.x, warp = tid>>5, lane = tid&31;
  int bm = blockIdx.y*128, bn = blockIdx.x*128;
  int wm = (warp>>2)*64, wn = (warp&3)*32;
  float c[4][4][4] = {};
  int frag_r = ((lane>>3)&1)*8 + (lane&7);
  int frag_k = (lane>>4)*8;

  int r2 = tid>>1, s2 = (tid&1)*16;
  const hf* pa0 = A  + (long)(bm+r2)*K + s2;
  const hf* pb0 = Bm + (long)(bn+r2)*K + s2;

  int T = K >> 5;
  cpa16(&As[0][r2*PITCH + s2],     pa0);
  cpa16(&As[0][r2*PITCH + s2 + 8], pa0 + 8);
  cpa16(&Bs[0][r2*PITCH + s2],     pb0);
  cpa16(&Bs[0][r2*PITCH + s2 + 8], pb0 + 8);
  cpa_commit();

  for(int t=0;t<T;t++){
    if(t+1<T){
      int k0 = (t+1)<<5;
      int st = (t+1)&1;
      cpa16(&As[st][r2*PITCH + s2],     pa0 + k0);
      cpa16(&As[st][r2*PITCH + s2 + 8], pa0 + k0 + 8);
      cpa16(&Bs[st][r2*PITCH + s2],     pb0 + k0);
      cpa16(&Bs[st][r2*PITCH + s2 + 8], pb0 + k0 + 8);
      cpa_commit();
      cpa_wait<1>();
    } else {
      cpa_wait<0>();
    }
    __syncthreads();
    int st = t&1;
#pragma unroll
    for(int kk=0;kk<32;kk+=16){
      uint32_t a4[4][4], b2[4][2];
#pragma unroll
      for(int mi=0;mi<4;mi++)
        ldsm4(a4[mi], &As[st][(wm+mi*16+frag_r)*PITCH + kk + frag_k]);
#pragma unroll
      for(int p=0;p<2;p++){
        uint32_t t4[4];
        ldsm4(t4, &Bs[st][(wn+p*16+frag_r)*PITCH + kk + frag_k]);
        b2[2*p][0]=t4[0]; b2[2*p][1]=t4[2]; b2[2*p+1][0]=t4[1]; b2[2*p+1][1]=t4[3];
      }
#pragma unroll
      for(int mi=0;mi<4;mi++)
#pragma unroll
        for(int ni=0;ni<4;ni++)
          mma_f16(c[mi][ni], a4[mi], b2[ni]);
    }
    __syncthreads();
  }
#pragma unroll
  for(int mi=0;mi<4;mi++)
#pragma unroll
  for(int ni=0;ni<4;ni++)
#pragma unroll
  for(int hh2=0;hh2<2;hh2++){
    int r = bm + wm + mi*16 + (lane>>2) + hh2*8;
    int cc = bn + wn + ni*8 + (lane&3)*2;
    float v0 = c[mi][ni][hh2*2+0], v1 = c[mi][ni][hh2*2+1];
    if(MODE==M_RES){
      v0 += bias[cc]   + res[(long)r*N + cc];
      v1 += bias[cc+1] + res[(long)r*N + cc + 1];
      *(float2*)&Cf[(long)r*N + cc] = make_float2(v0, v1);
    } else if(MODE==M_GELU){
      *(uint32_t*)&Ch[(long)r*N + cc] = packh2(gelu_f(v0 + bias[cc]), gelu_f(v1 + bias[cc+1]));
    } else if(MODE==M_QKV){
      int buf = cc>>10, c10 = cc&1023;
      const float* bp = (buf==0)? bias : (buf==1)? bias2 : bias3;
      int bI = r>>10, l = r&1023, hd = c10>>7, d = c10&127;
      *(uint32_t*)&Ch[(long)buf*SQKV + (((long)(bI*Hh+hd))*Lq + l)*DKc + d]
          = packh2(v0 + bp[c10], v1 + bp[c10+1]);
    }
  }
}

// ---------------- fused attention kernel ----------------
// block: 32 query rows of one (b,h). phases:
//  P1 qr = q@rk^T -> smem fp16 [32][1024]
//  P2 raw = q@k^T -> smem fp16 [32][1024]
//  P3 s = (raw + qr[pm])*scale + ap, mask, softmax -> attn fp16 (overlays qr, xor-swizzled)
//  P4a out += attn@v (v streamed, ldmatrix.trans)
//  P4b per 16-row group: scatter attn->path fp32 (overlays raw), out += path@rv
#define KP 136                      // staging/q pitch in halves
#define STG_E (128*KP)              // 17408 halves per staging buffer
#define OFF_STG 0
#define OFF_Q   (2*STG_E*2)         // 69632 bytes
#define OFF_QR  (OFF_Q + 32*KP*2)   // 78336
#define OFF_SC  (OFF_QR + 32*1024*2)// 143872
#define FATTN_SMEM (OFF_SC + 16*1032*4 + 256)  // ~210 KB

// full-coverage chunk stage: 128 rows x 128 halves = 2048 16B segs, 8 per thread
#define STAGE_CHUNK(dstbuf, srcbase)                                   \
  _Pragma("unroll")                                                    \
  for(int i_=0;i_<8;i_++){                                             \
    int s_ = tid + i_*256, row_ = s_>>4, s8_ = (s_&15)*8;              \
    cpa16(&(dstbuf)[row_*KP + s8_], (srcbase) + (long)row_*DKc + s8_); \
  }

__global__ __launch_bounds__(256)
void fattn(const hf* __restrict__ qkv, const hf* __restrict__ rk, const hf* __restrict__ rv,
           const int* __restrict__ pm, const int* __restrict__ msk, const float* __restrict__ ap,
           hf* __restrict__ xn)
{
  extern __shared__ char smc[];
  hf* stg  = (hf*)(smc + OFF_STG);
  hf* qs   = (hf*)(smc + OFF_Q);
  hf* qrS  = (hf*)(smc + OFF_QR);     // P1 out; P3 overlays attn (same rows)
  hf* attn = (hf*)(smc + OFF_QR);     // fp16 [32][1024], xor swizzle per 8 rows
  hf* scS  = (hf*)(smc + OFF_SC);     // P2 raw qk fp16 [32][1024]
  float* path = (float*)(smc + OFF_SC); // P4b fp32 [16][1032]

  int tid = threadIdx.x, warp = tid>>5, lane = tid&31;
  int frag_r = ((lane>>3)&1)*8 + (lane&7);
  int frag_k = (lane>>4)*8;
  int bh = blockIdx.y, b = bh>>3, hd = bh&7;
  int bm = blockIdx.x*32;

  const hf* q  = qkv + (long)bh*Lq*DKc;
  const hf* k  = qkv + SQKV + (long)bh*Lq*DKc;
  const hf* v  = qkv + 2*SQKV + (long)bh*Lq*DKc;
  const hf* rkp = rk + (long)bh*Pp*DKc;
  const hf* rvp = rv + (long)bh*Pp*DKc;

  // ---- load q tile [32][128]: 512 segs, 2 per thread ----
  {
#pragma unroll
    for(int i=0;i<2;i++){
      int s = tid + i*256, row = s>>4, s8 = (s&15)*8;
      cpa16(&qs[row*KP + s8], q + (long)(bm+row)*DKc + s8);
    }
    cpa_commit(); cpa_wait<0>();
  }
  __syncthreads();

  // persistent q a-fragments: [2 Mtiles][8 ksteps][4]
  uint32_t af[2][8][4];
#pragma unroll
  for(int mt=0; mt<2; mt++)
#pragma unroll
    for(int ks=0; ks<8; ks++)
      ldsm4(af[mt][ks], &qs[(mt*16+frag_r)*KP + ks*16 + frag_k]);

  int wn = warp*16;

  // ---- P1 & P2: two streamed NT GEMMs (rk then k), results to smem fp16 ----
#pragma unroll 1
  for(int ph=0; ph<2; ph++){
    const hf* src = (ph==0)? rkp : k;
    hf* outp = (ph==0)? qrS : scS;
    STAGE_CHUNK(stg, src)
    cpa_commit();
    for(int c=0;c<8;c++){
      if(c+1<8){
        hf* dst = stg + ((c+1)&1)*STG_E;
        const hf* s0 = src + (long)(c+1)*128*DKc;
        STAGE_CHUNK(dst, s0)
        cpa_commit();
        cpa_wait<1>();
      } else cpa_wait<0>();
      __syncthreads();
      hf* Bc = stg + (c&1)*STG_E;
      float S[2][2][4] = {};
#pragma unroll
      for(int ks=0;ks<8;ks++){
        uint32_t t4[4], b2[2][2];
        ldsm4(t4, &Bc[(wn+frag_r)*KP + ks*16 + frag_k]);
        b2[0][0]=t4[0]; b2[0][1]=t4[2]; b2[1][0]=t4[1]; b2[1][1]=t4[3];
#pragma unroll
        for(int mt=0;mt<2;mt++)
#pragma unroll
          for(int n8=0;n8<2;n8++)
            mma_f16(S[mt][n8], af[mt][ks], b2[n8]);
      }
#pragma unroll
      for(int mt=0;mt<2;mt++)
#pragma unroll
      for(int n8=0;n8<2;n8++)
#pragma unroll
      for(int hh2=0;hh2<2;hh2++){
        int row = mt*16 + (lane>>2) + hh2*8;
        int col = c*128 + wn + n8*8 + (lane&3)*2;
        *(uint32_t*)&outp[row*1024 + col] = packh2(S[mt][n8][hh2*2], S[mt][n8][hh2*2+1]);
      }
      __syncthreads();
    }
  }

  // ---- P3: gather + scale + ap + mask + softmax; write attn (xor swizzle) ----
  {
    const float scale = 0.08838834764831845f;
#pragma unroll 1
    for(int rr=0; rr<4; rr++){
      int row = warp*4 + rr;
      long gb = ((long)b*Lq + bm + row)*Lq;
      long ab = ((long)bh*Lq + bm + row)*Lq;
      float sv[32];
      float mx = -3.0e38f;
#pragma unroll
      for(int i=0;i<32;i++){
        int cc = lane + i*32;
        float qk = __half2float(scS[row*1024 + cc]);
        int p  = pm[gb + cc];
        int m  = msk[gb + cc];
        float apv = ap[ab + cc];
        float qrv = __half2float(qrS[row*1024 + p]);
        float s = (qk + qrv)*scale + apv;
        sv[i] = (m==0)? -1e9f : s;
        mx = fmaxf(mx, sv[i]);
      }
#pragma unroll
      for(int o=16;o>0;o>>=1) mx = fmaxf(mx, __shfl_xor_sync(0xffffffff, mx, o));
      float sum = 0.f;
#pragma unroll
      for(int i=0;i<32;i++){ sv[i] = expf(sv[i]-mx); sum += sv[i]; }
#pragma unroll
      for(int o=16;o>0;o>>=1) sum += __shfl_xor_sync(0xffffffff, sum, o);
      float inv = 1.f/sum;
      int rx = (row&7)<<3;
#pragma unroll
      for(int i=0;i<32;i++){
        int cc = lane + i*32;
        attn[row*1024 + (cc ^ rx)] = __float2half_rn(sv[i]*inv);
      }
    }
  }
  __syncthreads();

  float out[2][2][4] = {};

  // ---- P4a: out += attn @ v  (v streamed natural layout, trans b-frags) ----
  {
    STAGE_CHUNK(stg, v)
    cpa_commit();
    for(int c=0;c<8;c++){
      if(c+1<8){
        hf* dst = stg + ((c+1)&1)*STG_E;
        const hf* s0 = v + (long)(c+1)*128*DKc;
        STAGE_CHUNK(dst, s0)
        cpa_commit(); cpa_wait<1>();
      } else cpa_wait<0>();
      __syncthreads();
      hf* Bc = stg + (c&1)*STG_E;
#pragma unroll
      for(int ks=0;ks<8;ks++){
        uint32_t b2[2][2];
        { uint32_t t4[4];
          ldsm4t(t4, &Bc[(ks*16+frag_r)*KP + wn + frag_k]);
          b2[0][0]=t4[0]; b2[0][1]=t4[1]; b2[1][0]=t4[2]; b2[1][1]=t4[3]; }
#pragma unroll
        for(int mt=0;mt<2;mt++){
          uint32_t a4[4];
          int row = mt*16 + frag_r;
          int colh = c*128 + ks*16 + frag_k;
          ldsm4(a4, &attn[row*1024 + (colh ^ ((row&7)<<3))]);
#pragma unroll
          for(int n8=0;n8<2;n8++)
            mma_f16(out[mt][n8], a4, b2[n8]);
        }
      }
      __syncthreads();
    }
  }

  // ---- P4b: per 16-row group: scatter -> path fp32, out += path @ rv ----
#pragma unroll 1
  for(int g=0; g<2; g++){
    for(int i=tid; i<16*1032; i+=256) path[i] = 0.f;
    __syncthreads();
    for(int i=0;i<64;i++){
      int e = i*256 + tid;             // 16384 elements
      int row = g*16 + (e>>10), cc = e&1023;
      float a = __half2float(attn[row*1024 + (cc ^ ((row&7)<<3))]);
      int p = pm[((long)b*Lq + bm + row)*Lq + cc];
      atomicAdd(&path[(row - g*16)*1032 + p], a);
    }
    __syncthreads();
    STAGE_CHUNK(stg, rvp)
    cpa_commit();
    for(int c=0;c<8;c++){
      if(c+1<8){
        hf* dst = stg + ((c+1)&1)*STG_E;
        const hf* s0 = rvp + (long)(c+1)*128*DKc;
        STAGE_CHUNK(dst, s0)
        cpa_commit(); cpa_wait<1>();
      } else cpa_wait<0>();
      __syncthreads();
      hf* Bc = stg + (c&1)*STG_E;
#pragma unroll
      for(int ks=0;ks<8;ks++){
        uint32_t b2[2][2];
        { uint32_t t4[4];
          ldsm4t(t4, &Bc[(ks*16+frag_r)*KP + wn + frag_k]);
          b2[0][0]=t4[0]; b2[0][1]=t4[1]; b2[1][0]=t4[2]; b2[1][1]=t4[3]; }
        uint32_t a4[4];
        int r0 = lane>>2, c0 = c*128 + ks*16 + (lane&3)*2;
        a4[0] = packh2(path[r0*1032 + c0],     path[r0*1032 + c0+1]);
        a4[1] = packh2(path[(r0+8)*1032 + c0], path[(r0+8)*1032 + c0+1]);
        a4[2] = packh2(path[r0*1032 + c0+8],   path[r0*1032 + c0+9]);
        a4[3] = packh2(path[(r0+8)*1032 + c0+8], path[(r0+8)*1032 + c0+9]);
#pragma unroll
        for(int n8=0;n8<2;n8++)
          mma_f16(out[g][n8], a4, b2[n8]);
      }
      __syncthreads();
    }
  }

  // ---- write merged-head fp16 ----
#pragma unroll
  for(int mt=0;mt<2;mt++)
#pragma unroll
  for(int n8=0;n8<2;n8++)
#pragma unroll
  for(int hh2=0;hh2<2;hh2++){
    int row = bm + mt*16 + (lane>>2) + hh2*8;
    int dim = wn + n8*8 + (lane&3)*2;
    *(uint32_t*)&xn[((long)b*Lq + row)*Dd + hd*DKc + dim]
        = packh2(out[mt][n8][hh2*2], out[mt][n8][hh2*2+1]);
  }
}

// ---------------- LayerNorm -> fp16 ----------------
__global__ void ln_h(const float* __restrict__ x, const float* __restrict__ g,
                     const float* __restrict__ b, hf* __restrict__ y){
  __shared__ float red[256];
  int row = blockIdx.x;
  const float* xr = x + (size_t)row*Dd;
  float v[4]; float s = 0.f;
#pragma unroll
  for(int i=0;i<4;i++){ v[i] = xr[threadIdx.x + i*256]; s += v[i]; }
  red[threadIdx.x] = s; __syncthreads();
  for(int o=128;o>0;o>>=1){ if(threadIdx.x<o) red[threadIdx.x]+=red[threadIdx.x+o]; __syncthreads(); }
  float mean = red[0]*(1.f/Dd); __syncthreads();
  float s2 = 0.f;
#pragma unroll
  for(int i=0;i<4;i++){ float d = v[i]-mean; s2 += d*d; }
  red[threadIdx.x] = s2; __syncthreads();
  for(int o=128;o>0;o>>=1){ if(threadIdx.x<o) red[threadIdx.x]+=red[threadIdx.x+o]; __syncthreads(); }
  float inv = rsqrtf(red[0]*(1.f/Dd) + 1e-6f);
#pragma unroll
  for(int i=0;i<4;i++){
    int cidx = threadIdx.x + i*256;
    y[(long)row*Dd + cidx] = __float2half_rn(g[cidx]*(v[i]-mean)*inv + b[cidx]);
  }
}

// ---------------- weight prep ----------------
__global__ void tr_many(const float* __restrict__ wq, const float* __restrict__ wk,
                        const float* __restrict__ wv, const float* __restrict__ wo,
                        hf* __restrict__ o4){
  __shared__ float t[32][33];
  long z = blockIdx.z;
  const float* in = (z==0)? wq : (z==1)? wk : (z==2)? wv : wo;
  hf* o = o4 + z*(long)Dd*Dd;
  int bx = blockIdx.x*32, by = blockIdx.y*32;
  int tx = threadIdx.x, ty = threadIdx.y;
#pragma unroll
  for(int i=0;i<4;i++)
    t[ty+i*8][tx] = in[(long)(by+ty+i*8)*Dd + bx+tx];
  __syncthreads();
#pragma unroll
  for(int i=0;i<4;i++)
    o[(long)(bx+ty+i*8)*Dd + by+tx] = __float2half_rn(t[tx][ty+i*8]);
}
__global__ void tr_h(const float* __restrict__ in, hf* __restrict__ o,
                     int rows, int cols){
  __shared__ float t[32][33];
  int bx = blockIdx.x*32, by = blockIdx.y*32;
  int tx = threadIdx.x, ty = threadIdx.y;
#pragma unroll
  for(int i=0;i<4;i++)
    t[ty+i*8][tx] = in[(long)(by+ty+i*8)*cols + bx+tx];
  __syncthreads();
#pragma unroll
  for(int i=0;i<4;i++)
    o[(long)(bx+ty+i*8)*rows + by+tx] = __float2half_rn(t[tx][ty+i*8]);
}
__global__ void conv_r(const float* __restrict__ a, const float* __restrict__ bsrc,
                       hf* __restrict__ oa, hf* __restrict__ ob){
  int idx = blockIdx.x*256 + threadIdx.x;
  oa[idx] = __float2half_rn(a[idx]);
  ob[idx] = __float2half_rn(bsrc[idx]);
}

// ---------------- launch ----------------
extern "C" void kernel_launch(void* const* d_in, const int* in_sizes, int n_in,
                              void* d_out, int out_size){
  const float* content = (const float*)d_in[0];
  const int*   mask    = (const int*)  d_in[1];
  const float* r_k     = (const float*)d_in[2];
  const float* r_v     = (const float*)d_in[3];
  const int*   path_map= (const int*)  d_in[4];
  const float* ap      = (const float*)d_in[5];
  const float* wq = (const float*)d_in[6];  const float* bq = (const float*)d_in[7];
  const float* wk = (const float*)d_in[8];  const float* bk = (const float*)d_in[9];
  const float* wv = (const float*)d_in[10]; const float* bv = (const float*)d_in[11];
  const float* wo = (const float*)d_in[12]; const float* bo = (const float*)d_in[13];
  const float* ln1g = (const float*)d_in[14]; const float* ln1b = (const float*)d_in[15];
  const float* ln2g = (const float*)d_in[16]; const float* ln2b = (const float*)d_in[17];
  const float* w1 = (const float*)d_in[18]; const float* b1 = (const float*)d_in[19];
  const float* w2 = (const float*)d_in[20]; const float* b2 = (const float*)d_in[21];
  float* out = (float*)d_out;

  hf *xn,*qkv,*h,*w4t,*w1t,*w2t,*rk,*rv;
  float *x;
  cudaGetSymbolAddress((void**)&xn, g_xn);
  cudaGetSymbolAddress((void**)&qkv, g_qkv);
  cudaGetSymbolAddress((void**)&h, g_h);
  cudaGetSymbolAddress((void**)&w4t, g_w4t);
  cudaGetSymbolAddress((void**)&w1t, g_w1t); cudaGetSymbolAddress((void**)&w2t, g_w2t);
  cudaGetSymbolAddress((void**)&rk, g_rk);   cudaGetSymbolAddress((void**)&rv, g_rv);
  cudaGetSymbolAddress((void**)&x, g_x);

  cudaFuncSetAttribute(fattn, cudaFuncAttributeMaxDynamicSharedMemorySize, FATTN_SMEM);

  dim3 tb(32,8);
  // prep
  tr_many<<<dim3(Dd/32, Dd/32, 4), tb>>>(wq, wk, wv, wo, w4t);
  tr_h<<<dim3(Ff/32, Dd/32), tb>>>(w1, w1t, Dd, Ff);
  tr_h<<<dim3(Dd/32, Ff/32), tb>>>(w2, w2t, Ff, Dd);
  conv_r<<<(Bb*Hh*Pp*DKc)/256, 256>>>(r_k, r_v, rk, rv);

  // LN1
  ln_h<<<Bb*Lq, 256>>>(content, ln1g, ln1b, xn);

  // QKV (N=3072)
  hgemm<M_QKV><<<dim3(3*Dd/128, (Bb*Lq)/128),256>>>(
      xn, w4t, bq, bk, bv, nullptr, nullptr, qkv, 3*Dd, Dd);

  // fused attention -> xn (merged heads fp16)
  fattn<<<dim3(Lq/32, Bb*Hh), 256, FATTN_SMEM>>>(
      qkv, rk, rv, path_map, mask, ap, xn);

  // x = xn@wo + bo + content
  hgemm<M_RES><<<dim3(Dd/128,(Bb*Lq)/128),256>>>(
      xn, w4t + 3*(long)Dd*Dd, bo, nullptr, nullptr, content, x, nullptr, Dd, Dd);

  // LN2
  ln_h<<<Bb*Lq, 256>>>(x, ln2g, ln2b, xn);

  // h = gelu(xn@w1 + b1)
  hgemm<M_GELU><<<dim3(Ff/128,(Bb*Lq)/128),256>>>(
      xn, w1t, b1, nullptr, nullptr, nullptr, nullptr, h, Ff, Dd);

  // out = h@w2 + b2 + x
  hgemm<M_RES><<<dim3(Dd/128,(Bb*Lq)/128),256>>>(
      h, w2t, b2, nullptr, nullptr, x, out, nullptr, Dd, Ff);
}

// round 12
// speedup vs baseline: 1.0996x; 1.0996x over previous
#include <cuda_runtime.h>
#include <cuda_fp16.h>
#include <cstdint>
#include <math.h>

typedef __half hf;

#define Bb 4
#define Lq 1024
#define Dd 1024
#define Hh 8
#define Pp 1024
#define Ff 4096
#define DKc 128

#define SQKV ((long)Bb*Hh*Lq*DKc)

// ---------------- scratch ----------------
__device__ hf g_xn[Bb*Lq*Dd];
__device__ hf g_qkv[3*Bb*Hh*Lq*DKc];      // q | k | v, each [B,H,L,DK]
__device__ hf g_vt[Bb*Hh*Lq*DKc];         // [bh][DK][L]
__device__ hf g_h [Bb*Lq*Ff];
__device__ hf g_attn[(size_t)Bb*Hh*Lq*Lq];
__device__ hf g_path[(size_t)Bb*Hh*Lq*Pp];
__device__ hf g_w4t[4*Dd*Dd];             // wq^T | wk^T | wv^T | wo^T
__device__ hf g_w1t[Dd*Ff], g_w2t[Dd*Ff];
__device__ hf g_rk [Bb*Hh*Pp*DKc];
__device__ hf g_rvt[Bb*Hh*Pp*DKc];
__device__ hf g_scores[(size_t)Bb*Hh*Lq*Lq];   // fp16 final scores
__device__ hf g_qr[(size_t)Bb*Hh*Lq*Pp];       // fp16 qr
__device__ float g_x[Bb*Lq*Dd];

// ---------------- helpers ----------------
__device__ __forceinline__ void ldsm4(uint32_t r[4], const hf* p){
  uint32_t a = (uint32_t)__cvta_generic_to_shared(p);
  asm volatile("ldmatrix.sync.aligned.m8n8.x4.shared.b16 {%0,%1,%2,%3},[%4];"
    :"=r"(r[0]),"=r"(r[1]),"=r"(r[2]),"=r"(r[3]):"r"(a));
}
__device__ __forceinline__ void mma_f16(float c[4], const uint32_t a[4], const uint32_t b[2]){
  asm volatile("mma.sync.aligned.m16n8k16.row.col.f32.f16.f16.f32 "
    "{%0,%1,%2,%3},{%4,%5,%6,%7},{%8,%9},{%0,%1,%2,%3};"
    :"+f"(c[0]),"+f"(c[1]),"+f"(c[2]),"+f"(c[3])
    :"r"(a[0]),"r"(a[1]),"r"(a[2]),"r"(a[3]),"r"(b[0]),"r"(b[1]));
}
__device__ __forceinline__ void cpa16(hf* dst, const hf* src){
  uint32_t d = (uint32_t)__cvta_generic_to_shared(dst);
  asm volatile("cp.async.cg.shared.global [%0],[%1],16;"::"r"(d),"l"(src));
}
__device__ __forceinline__ void cpa_commit(){ asm volatile("cp.async.commit_group;"); }
template<int N> __device__ __forceinline__ void cpa_wait(){ asm volatile("cp.async.wait_group %0;"::"n"(N)); }

__device__ __forceinline__ float gelu_f(float u){
  return 0.5f*u*(1.f + tanhf(0.7978845608028654f*(u + 0.044715f*u*u*u)));
}
__device__ __forceinline__ uint32_t packh2(float a, float b){
  __half2 h; h.x = __float2half_rn(a); h.y = __float2half_rn(b);
  return *(uint32_t*)&h;
}

// ---------------- fp16 tensor-core GEMM, 2-stage cp.async pipeline ----------------
// A[M][K] row-major fp16, B[N][K] row-major fp16 (pre-transposed). 128x128 tile, 8 warps.
// Optional second K-segment (A2/B2, K2) accumulated in registers (M_MERGE).
#define M_HOUT  0
#define M_QKV   2
#define M_GELU  3
#define M_RES   4
#define M_SCORE 5
#define M_MERGE 6

#define PITCH 40
#define PLANE (128*PITCH)

template<int MODE>
__global__ __launch_bounds__(256)
void hgemm(const hf* __restrict__ A, const hf* __restrict__ Bm,
           const hf* __restrict__ A2, const hf* __restrict__ B2,
           const float* __restrict__ bias, const float* __restrict__ bias2,
           const float* __restrict__ bias3,
           const float* __restrict__ res,
           const int* __restrict__ pm, const int* __restrict__ msk,
           const hf* __restrict__ qrh,
           float* __restrict__ Cf, hf* __restrict__ Ch,
           int N, int K, int K2,
           long sA, long sB, long sA2, long sB2, long sC)
{
  __shared__ hf As[2][PLANE];
  __shared__ hf Bs[2][PLANE];
  long z = blockIdx.z;
  long cbase = z*sC;
  int tid = threadIdx.x, warp = tid>>5, lane = tid&31;
  int bm = blockIdx.y*128, bn = blockIdx.x*128;
  int wm = (warp>>2)*64, wn = (warp&3)*32;
  float c[4][4][4] = {};
  int frag_r = ((lane>>3)&1)*8 + (lane&7);
  int frag_k = (lane>>4)*8;

  int r2 = tid>>1, s2 = (tid&1)*16;
  const hf* pa1 = A  + z*sA + (long)(bm+r2)*K + s2;
  const hf* pb1 = Bm + z*sB + (long)(bn+r2)*K + s2;
  const hf* pa2 = (MODE==M_MERGE) ? (A2 + z*sA2 + (long)(bm+r2)*K2 + s2) : pa1;
  const hf* pb2 = (MODE==M_MERGE) ? (B2 + z*sB2 + (long)(bn+r2)*K2 + s2) : pb1;

  const int T1 = K >> 5;
  const int T  = T1 + (K2 >> 5);

  auto ld = [&](int cchunk){
    int st = cchunk&1;
    const hf *pa, *pb; int off;
    if(cchunk < T1){ pa = pa1; pb = pb1; off = cchunk<<5; }
    else           { pa = pa2; pb = pb2; off = (cchunk-T1)<<5; }
    cpa16(&As[st][r2*PITCH + s2],     pa + off);
    cpa16(&As[st][r2*PITCH + s2 + 8], pa + off + 8);
    cpa16(&Bs[st][r2*PITCH + s2],     pb + off);
    cpa16(&Bs[st][r2*PITCH + s2 + 8], pb + off + 8);
  };

  ld(0); cpa_commit();
  for(int t=0;t<T;t++){
    if(t+1<T){
      ld(t+1); cpa_commit();
      cpa_wait<1>();
    } else {
      cpa_wait<0>();
    }
    __syncthreads();
    int st = t&1;
#pragma unroll
    for(int kk=0;kk<32;kk+=16){
      uint32_t a4[4][4], b2[4][2];
#pragma unroll
      for(int mi=0;mi<4;mi++)
        ldsm4(a4[mi], &As[st][(wm+mi*16+frag_r)*PITCH + kk + frag_k]);
#pragma unroll
      for(int p=0;p<2;p++){
        uint32_t t4[4];
        ldsm4(t4, &Bs[st][(wn+p*16+frag_r)*PITCH + kk + frag_k]);
        b2[2*p][0]=t4[0]; b2[2*p][1]=t4[2]; b2[2*p+1][0]=t4[1]; b2[2*p+1][1]=t4[3];
      }
#pragma unroll
      for(int mi=0;mi<4;mi++)
#pragma unroll
        for(int ni=0;ni<4;ni++)
          mma_f16(c[mi][ni], a4[mi], b2[ni]);
    }
    __syncthreads();
  }
  // epilogue
#pragma unroll
  for(int mi=0;mi<4;mi++)
#pragma unroll
  for(int ni=0;ni<4;ni++)
#pragma unroll
  for(int hh2=0;hh2<2;hh2++){
    int r = bm + wm + mi*16 + (lane>>2) + hh2*8;
    int cc = bn + wn + ni*8 + (lane&3)*2;
    float v0 = c[mi][ni][hh2*2+0], v1 = c[mi][ni][hh2*2+1];
    if(MODE==M_HOUT){
      *(uint32_t*)&Ch[cbase + (long)r*N + cc] = packh2(v0, v1);
    } else if(MODE==M_RES){
      v0 += bias[cc]   + res[(long)r*N + cc];
      v1 += bias[cc+1] + res[(long)r*N + cc + 1];
      *(float2*)&Cf[cbase + (long)r*N + cc] = make_float2(v0, v1);
    } else if(MODE==M_GELU){
      *(uint32_t*)&Ch[(long)r*N + cc] = packh2(gelu_f(v0 + bias[cc]), gelu_f(v1 + bias[cc+1]));
    } else if(MODE==M_QKV){
      int buf = cc>>10, c10 = cc&1023;
      const float* bp = (buf==0)? bias : (buf==1)? bias2 : bias3;
      int bI = r>>10, l = r&1023, hd = c10>>7, d = c10&127;
      *(uint32_t*)&Ch[(long)buf*SQKV + (((long)(bI*Hh+hd))*Lq + l)*DKc + d]
          = packh2(v0 + bp[c10], v1 + bp[c10+1]);
    } else if(MODE==M_MERGE){
      long bI = z>>3, hd = z&7;
      *(uint32_t*)&Ch[((bI*Lq + r))*Dd + hd*DKc + cc] = packh2(v0, v1);
    } else if(MODE==M_SCORE){
      const float scale = 0.08838834764831845f;
      long bI = z >> 3;
      long rowq = z*((long)Lq*Pp) + (long)r*Pp;
      long rowm = bI*((long)Lq*Lq) + (long)r*Lq;
      long rowa = z*((long)Lq*Lq) + (long)r*Lq;
      int p0 = pm[rowm + cc], p1 = pm[rowm + cc + 1];
      int m0 = msk[rowm + cc], m1 = msk[rowm + cc + 1];
      float s0v = (v0 + __half2float(qrh[rowq + p0]))*scale + res[rowa + cc];
      float s1v = (v1 + __half2float(qrh[rowq + p1]))*scale + res[rowa + cc + 1];
      if(m0==0) s0v = -60000.f;
      if(m1==0) s1v = -60000.f;
      *(uint32_t*)&Ch[cbase + (long)r*N + cc] = packh2(s0v, s1v);
    }
  }
}

// ---------------- LayerNorm -> fp16 ----------------
__global__ void ln_h(const float* __restrict__ x, const float* __restrict__ g,
                     const float* __restrict__ b, hf* __restrict__ y){
  __shared__ float red[256];
  int row = blockIdx.x;
  const float* xr = x + (size_t)row*Dd;
  float v[4]; float s = 0.f;
#pragma unroll
  for(int i=0;i<4;i++){ v[i] = xr[threadIdx.x + i*256]; s += v[i]; }
  red[threadIdx.x] = s; __syncthreads();
  for(int o=128;o>0;o>>=1){ if(threadIdx.x<o) red[threadIdx.x]+=red[threadIdx.x+o]; __syncthreads(); }
  float mean = red[0]*(1.f/Dd); __syncthreads();
  float s2 = 0.f;
#pragma unroll
  for(int i=0;i<4;i++){ float d = v[i]-mean; s2 += d*d; }
  red[threadIdx.x] = s2; __syncthreads();
  for(int o=128;o>0;o>>=1){ if(threadIdx.x<o) red[threadIdx.x]+=red[threadIdx.x+o]; __syncthreads(); }
  float inv = rsqrtf(red[0]*(1.f/Dd) + 1e-6f);
#pragma unroll
  for(int i=0;i<4;i++){
    int cidx = threadIdx.x + i*256;
    y[(long)row*Dd + cidx] = __float2half_rn(g[cidx]*(v[i]-mean)*inv + b[cidx]);
  }
}

// ---------------- weight prep ----------------
__global__ void tr_many(const float* __restrict__ wq, const float* __restrict__ wk,
                        const float* __restrict__ wv, const float* __restrict__ wo,
                        hf* __restrict__ o4){
  __shared__ float t[32][33];
  long z = blockIdx.z;
  const float* in = (z==0)? wq : (z==1)? wk : (z==2)? wv : wo;
  hf* o = o4 + z*(long)Dd*Dd;
  int bx = blockIdx.x*32, by = blockIdx.y*32;
  int tx = threadIdx.x, ty = threadIdx.y;
#pragma unroll
  for(int i=0;i<4;i++)
    t[ty+i*8][tx] = in[(long)(by+ty+i*8)*Dd + bx+tx];
  __syncthreads();
#pragma unroll
  for(int i=0;i<4;i++)
    o[(long)(bx+ty+i*8)*Dd + by+tx] = __float2half_rn(t[tx][ty+i*8]);
}
__global__ void tr_h(const float* __restrict__ in, hf* __restrict__ o,
                     int rows, int cols){
  __shared__ float t[32][33];
  int bx = blockIdx.x*32, by = blockIdx.y*32;
  int tx = threadIdx.x, ty = threadIdx.y;
#pragma unroll
  for(int i=0;i<4;i++)
    t[ty+i*8][tx] = in[(long)(by+ty+i*8)*cols + bx+tx];
  __syncthreads();
#pragma unroll
  for(int i=0;i<4;i++)
    o[(long)(bx+ty+i*8)*rows + by+tx] = __float2half_rn(t[tx][ty+i*8]);
}
// per-head: convert rk (straight) + transpose rv
__global__ void prep_r(const float* __restrict__ rk, const float* __restrict__ rv,
                       hf* __restrict__ rkh, hf* __restrict__ rvt){
  __shared__ float t[32][33];
  long z = blockIdx.z;
  const float* ik = rk + z*(long)Pp*DKc;
  const float* iv = rv + z*(long)Pp*DKc;
  hf* ok = rkh + z*(long)Pp*DKc;
  hf* ov = rvt + z*(long)Pp*DKc;
  int bx = blockIdx.x*32, by = blockIdx.y*32;  // bx: DKc, by: Pp
  int tx = threadIdx.x, ty = threadIdx.y;
#pragma unroll
  for(int i=0;i<4;i++){
    long src = (long)(by+ty+i*8)*DKc + bx+tx;
    t[ty+i*8][tx] = iv[src];
    ok[src] = __float2half_rn(ik[src]);
  }
  __syncthreads();
#pragma unroll
  for(int i=0;i<4;i++)
    ov[(long)(bx+ty+i*8)*Pp + by+tx] = __float2half_rn(t[tx][ty+i*8]);
}
// v -> vt [bh][DK][L] (fp16 transpose)
__global__ void tr_h16(const hf* __restrict__ in, hf* __restrict__ o,
                       int rows, int cols, long s){
  __shared__ hf t[32][33];
  long z = blockIdx.z;
  in += z*s; o += z*s;
  int bx = blockIdx.x*32, by = blockIdx.y*32;
  int tx = threadIdx.x, ty = threadIdx.y;
#pragma unroll
  for(int i=0;i<4;i++)
    t[ty+i*8][tx] = in[(long)(by+ty+i*8)*cols + bx+tx];
  __syncthreads();
#pragma unroll
  for(int i=0;i<4;i++)
    o[(long)(bx+ty+i*8)*rows + by+tx] = t[tx][ty+i*8];
}

// ---------------- fused softmax + scatter (fp16 scores in) ----------------
__global__ void softmax_scatter(const hf* __restrict__ scores, const int* __restrict__ pm,
                                hf* __restrict__ outa, hf* __restrict__ outp){
  __shared__ float red[256];
  __shared__ float sp[Pp];
  int bh = blockIdx.y;
  int b  = bh >> 3;
  int i  = blockIdx.x;
  const hf*  srow = scores + ((size_t)bh*Lq + i)*Lq;
  const int* prow = pm + ((size_t)b*Lq + i)*Lq;
#pragma unroll
  for(int k=0;k<4;k++) sp[threadIdx.x + k*256] = 0.f;
  float v[4]; float mx = -3.0e38f;
#pragma unroll
  for(int k=0;k<4;k++){
    v[k] = __half2float(srow[threadIdx.x + k*256]);
    mx = fmaxf(mx, v[k]);
  }
  red[threadIdx.x] = mx; __syncthreads();
  for(int o=128;o>0;o>>=1){ if(threadIdx.x<o) red[threadIdx.x]=fmaxf(red[threadIdx.x],red[threadIdx.x+o]); __syncthreads(); }
  mx = red[0]; __syncthreads();
  float s = 0.f;
#pragma unroll
  for(int k=0;k<4;k++){ v[k] = expf(v[k]-mx); s += v[k]; }
  red[threadIdx.x] = s; __syncthreads();
  for(int o=128;o>0;o>>=1){ if(threadIdx.x<o) red[threadIdx.x]+=red[threadIdx.x+o]; __syncthreads(); }
  float inv = 1.f/red[0];
  long obase = ((size_t)bh*Lq + i)*Lq;
#pragma unroll
  for(int k=0;k<4;k++){
    int j = threadIdx.x + k*256;
    float a = v[k]*inv;
    outa[obase + j] = __float2half_rn(a);
    atomicAdd(&sp[prow[j]], a);
  }
  __syncthreads();
  long pbase = ((size_t)bh*Lq + i)*Pp;
#pragma unroll
  for(int k=0;k<4;k++){
    int cidx = threadIdx.x + k*256;
    outp[pbase + cidx] = __float2half_rn(sp[cidx]);
  }
}

// ---------------- launch ----------------
extern "C" void kernel_launch(void* const* d_in, const int* in_sizes, int n_in,
                              void* d_out, int out_size){
  const float* content = (const float*)d_in[0];
  const int*   mask    = (const int*)  d_in[1];
  const float* r_k     = (const float*)d_in[2];
  const float* r_v     = (const float*)d_in[3];
  const int*   path_map= (const int*)  d_in[4];
  const float* ap      = (const float*)d_in[5];
  const float* wq = (const float*)d_in[6];  const float* bq = (const float*)d_in[7];
  const float* wk = (const float*)d_in[8];  const float* bk = (const float*)d_in[9];
  const float* wv = (const float*)d_in[10]; const float* bv = (const float*)d_in[11];
  const float* wo = (const float*)d_in[12]; const float* bo = (const float*)d_in[13];
  const float* ln1g = (const float*)d_in[14]; const float* ln1b = (const float*)d_in[15];
  const float* ln2g = (const float*)d_in[16]; const float* ln2b = (const float*)d_in[17];
  const float* w1 = (const float*)d_in[18]; const float* b1 = (const float*)d_in[19];
  const float* w2 = (const float*)d_in[20]; const float* b2 = (const float*)d_in[21];
  float* out = (float*)d_out;

  hf *xn,*qkv,*vt,*h,*at,*pt,*w4t,*w1t,*w2t,*rk,*rvt,*sc,*qr;
  float *x;
  cudaGetSymbolAddress((void**)&xn, g_xn);
  cudaGetSymbolAddress((void**)&qkv, g_qkv);
  cudaGetSymbolAddress((void**)&vt, g_vt);
  cudaGetSymbolAddress((void**)&h, g_h);
  cudaGetSymbolAddress((void**)&at, g_attn); cudaGetSymbolAddress((void**)&pt, g_path);
  cudaGetSymbolAddress((void**)&w4t, g_w4t);
  cudaGetSymbolAddress((void**)&w1t, g_w1t); cudaGetSymbolAddress((void**)&w2t, g_w2t);
  cudaGetSymbolAddress((void**)&rk, g_rk);   cudaGetSymbolAddress((void**)&rvt, g_rvt);
  cudaGetSymbolAddress((void**)&sc, g_scores);
  cudaGetSymbolAddress((void**)&qr, g_qr);
  cudaGetSymbolAddress((void**)&x, g_x);

  hf* q = qkv;
  hf* k = qkv + SQKV;
  hf* v = qkv + 2*SQKV;
  long sQK = (long)Lq*DKc;

  dim3 tb(32,8);
  // prep
  tr_many<<<dim3(Dd/32, Dd/32, 4), tb>>>(wq, wk, wv, wo, w4t);
  tr_h<<<dim3(Ff/32, Dd/32), tb>>>(w1, w1t, Dd, Ff);
  tr_h<<<dim3(Dd/32, Ff/32), tb>>>(w2, w2t, Ff, Dd);
  prep_r<<<dim3(DKc/32, Pp/32, Bb*Hh), tb>>>(r_k, r_v, rk, rvt);

  // LN1
  ln_h<<<Bb*Lq, 256>>>(content, ln1g, ln1b, xn);

  // combined QKV GEMM (N=3072)
  hgemm<M_QKV><<<dim3(3*Dd/128, (Bb*Lq)/128, 1),256>>>(
      xn, w4t, nullptr,nullptr, bq, bk, bv, nullptr, nullptr,nullptr, nullptr,
      nullptr, qkv, 3*Dd, Dd, 0, 0,0,0,0, 0);

  // v -> vt
  tr_h16<<<dim3(DKc/32, Lq/32, Bb*Hh), tb>>>(v, vt, Lq, DKc, sQK);

  // qr = q@rk^T  (fp16 out)
  hgemm<M_HOUT><<<dim3(Pp/128, Lq/128, Bb*Hh),256>>>(
      q, rk, nullptr,nullptr, nullptr,nullptr,nullptr, nullptr, nullptr,nullptr, nullptr,
      nullptr, qr, Pp, DKc, 0, sQK, (long)Pp*DKc, 0,0, (long)Lq*Pp);

  // scores = (q@k^T + gather(qr))*scale + ap, masked  (fp16 out)
  hgemm<M_SCORE><<<dim3(Lq/128, Lq/128, Bb*Hh),256>>>(
      q, k, nullptr,nullptr, nullptr, nullptr,nullptr, ap, path_map, mask, qr,
      nullptr, sc, Lq, DKc, 0, sQK, sQK, 0,0, (long)Lq*Lq);

  // fused softmax + scatter
  softmax_scatter<<<dim3(Lq, Bb*Hh),256>>>(sc, path_map, at, pt);

  // merged: out = attn@v + path@r_v -> xn (head-merged fp16)
  hgemm<M_MERGE><<<dim3(1, Lq/128, Bb*Hh),256>>>(
      at, vt, pt, rvt, nullptr,nullptr,nullptr, nullptr, nullptr,nullptr, nullptr,
      nullptr, xn, DKc, Lq, Pp,
      (long)Lq*Lq, (long)DKc*Lq, (long)Lq*Pp, (long)DKc*Pp, 0);

  // x = merged@wo + bo + content
  hgemm<M_RES><<<dim3(Dd/128,(Bb*Lq)/128,1),256>>>(
      xn, w4t + 3*(long)Dd*Dd, nullptr,nullptr, bo, nullptr,nullptr, content, nullptr,nullptr, nullptr,
      x, nullptr, Dd, Dd, 0, 0,0,0,0, 0);

  // LN2
  ln_h<<<Bb*Lq, 256>>>(x, ln2g, ln2b, xn);

  // h = gelu(xn@w1 + b1)
  hgemm<M_GELU><<<dim3(Ff/128,(Bb*Lq)/128,1),256>>>(
      xn, w1t, nullptr,nullptr, b1, nullptr,nullptr, nullptr, nullptr,nullptr, nullptr,
      nullptr, h, Ff, Dd, 0, 0,0,0,0, 0);

  // out = h@w2 + b2 + x
  hgemm<M_RES><<<dim3(Dd/128,(Bb*Lq)/128,1),256>>>(
      h, w2t, nullptr,nullptr, b2, nullptr,nullptr, x, nullptr,nullptr, nullptr,
      out, nullptr, Dd, Ff, 0, 0,0,0,0, 0);
}

// round 13
// speedup vs baseline: 1.2025x; 1.0936x over previous
#include <cuda_runtime.h>
#include <cuda_fp16.h>
#include <cstdint>
#include <math.h>

typedef __half hf;

#define Bb 4
#define Lq 1024
#define Dd 1024
#define Hh 8
#define Pp 1024
#define Ff 4096
#define DKc 128

#define SQKV ((long)Bb*Hh*Lq*DKc)

// ---------------- scratch ----------------
__device__ hf g_xn[Bb*Lq*Dd];
__device__ hf g_qkv[3*Bb*Hh*Lq*DKc];      // q | k | v, each [B,H,L,DK]
__device__ hf g_h [Bb*Lq*Ff];
__device__ hf g_attn[(size_t)Bb*Hh*Lq*Lq];
__device__ hf g_path[(size_t)Bb*Hh*Lq*Pp];
__device__ hf g_wc [Dd*3*Dd];             // [1024][3072] = wq|wk|wv columns, K-major
__device__ hf g_wo [Dd*Dd];               // K-major natural
__device__ hf g_w1 [Dd*Ff];               // K-major natural
__device__ hf g_w2 [Ff*Dd];               // K-major natural
__device__ hf g_rk [Bb*Hh*Pp*DKc];
__device__ hf g_rv [Bb*Hh*Pp*DKc];
__device__ hf g_scores[(size_t)Bb*Hh*Lq*Lq];   // fp16 final scores
__device__ hf g_qr[(size_t)Bb*Hh*Lq*Pp];       // fp16 qr
__device__ float g_x[Bb*Lq*Dd];

// ---------------- helpers ----------------
__device__ __forceinline__ void ldsm4(uint32_t r[4], const hf* p){
  uint32_t a = (uint32_t)__cvta_generic_to_shared(p);
  asm volatile("ldmatrix.sync.aligned.m8n8.x4.shared.b16 {%0,%1,%2,%3},[%4];"
    :"=r"(r[0]),"=r"(r[1]),"=r"(r[2]),"=r"(r[3]):"r"(a));
}
__device__ __forceinline__ void ldsm4t(uint32_t r[4], const hf* p){
  uint32_t a = (uint32_t)__cvta_generic_to_shared(p);
  asm volatile("ldmatrix.sync.aligned.m8n8.x4.trans.shared.b16 {%0,%1,%2,%3},[%4];"
    :"=r"(r[0]),"=r"(r[1]),"=r"(r[2]),"=r"(r[3]):"r"(a));
}
__device__ __forceinline__ void mma_f16(float c[4], const uint32_t a[4], const uint32_t b[2]){
  asm volatile("mma.sync.aligned.m16n8k16.row.col.f32.f16.f16.f32 "
    "{%0,%1,%2,%3},{%4,%5,%6,%7},{%8,%9},{%0,%1,%2,%3};"
    :"+f"(c[0]),"+f"(c[1]),"+f"(c[2]),"+f"(c[3])
    :"r"(a[0]),"r"(a[1]),"r"(a[2]),"r"(a[3]),"r"(b[0]),"r"(b[1]));
}
__device__ __forceinline__ void cpa16(hf* dst, const hf* src){
  uint32_t d = (uint32_t)__cvta_generic_to_shared(dst);
  asm volatile("cp.async.cg.shared.global [%0],[%1],16;"::"r"(d),"l"(src));
}
__device__ __forceinline__ void cpa_commit(){ asm volatile("cp.async.commit_group;"); }
template<int N> __device__ __forceinline__ void cpa_wait(){ asm volatile("cp.async.wait_group %0;"::"n"(N)); }

__device__ __forceinline__ float gelu_f(float u){
  return 0.5f*u*(1.f + tanhf(0.7978845608028654f*(u + 0.044715f*u*u*u)));
}
__device__ __forceinline__ uint32_t packh2(float a, float b){
  __half2 h; h.x = __float2half_rn(a); h.y = __float2half_rn(b);
  return *(uint32_t*)&h;
}

// ---------------- fp16 tensor-core GEMM ----------------
// A[M][K] row-major. BTRANS=0: B[N][K] row-major (N-major). BTRANS=1: B[K][N]
// row-major (K-major, natural weights/v/rv), ldb == N, loaded via ldmatrix.trans.
// 128x128 tile, 8 warps, 2-stage cp.async. M_MERGE: 2nd K-segment accumulated.
#define M_HOUT  0
#define M_QKV   2
#define M_GELU  3
#define M_RES   4
#define M_SCORE 5
#define M_MERGE 6

#define PITCH 40
#define PLANE (128*PITCH)
#define BP    136

template<int MODE, int BTRANS>
__global__ __launch_bounds__(256)
void hgemm(const hf* __restrict__ A, const hf* __restrict__ Bm,
           const hf* __restrict__ A2, const hf* __restrict__ B2,
           const float* __restrict__ bias, const float* __restrict__ bias2,
           const float* __restrict__ bias3,
           const float* __restrict__ res,
           const int* __restrict__ pm, const int* __restrict__ msk,
           const hf* __restrict__ qrh,
           float* __restrict__ Cf, hf* __restrict__ Ch,
           int N, int K, int K2,
           long sA, long sB, long sA2, long sB2, long sC)
{
  __shared__ hf As[2][PLANE];
  __shared__ hf Bs[2][PLANE];
  long z = blockIdx.z;
  long cbase = z*sC;
  int tid = threadIdx.x, warp = tid>>5, lane = tid&31;
  int bm = blockIdx.y*128, bn = blockIdx.x*128;
  int wm = (warp>>2)*64, wn = (warp&3)*32;
  float c[4][4][4] = {};
  int frag_r = ((lane>>3)&1)*8 + (lane&7);
  int frag_k = (lane>>4)*8;

  // A staging coords (2 segs/thread)
  int r2 = tid>>1, s2 = (tid&1)*16;
  const hf* pa1 = A  + z*sA + (long)(bm+r2)*K + s2;
  const hf* pa2 = (MODE==M_MERGE) ? (A2 + z*sA2 + (long)(bm+r2)*K2 + s2) : pa1;
  // B staging coords
  // BTRANS=0: N-major rows, 2 segs/thread (same as A)
  const hf* pb1n = Bm + z*sB + (long)(bn+r2)*K + s2;
  const hf* pb2n = pb1n;
  // BTRANS=1: K-major: 1 seg/thread: row=tid>>3 (32 k-rows), col8=(tid&7)*16
  int br = tid>>3, bc8 = (tid&7)*16;
  const hf* pb1t = Bm + z*sB + (long)br*N + bn + bc8;
  const hf* pb2t = (MODE==M_MERGE) ? (B2 + z*sB2 + (long)br*N + bn + bc8) : pb1t;

  const int T1 = K >> 5;
  const int T  = T1 + (K2 >> 5);

  auto ld = [&](int cchunk){
    int st = cchunk&1;
    int off;
    bool seg1 = (cchunk < T1);
    off = seg1 ? (cchunk<<5) : ((cchunk-T1)<<5);
    {
      const hf* pa = seg1 ? pa1 : pa2;
      cpa16(&As[st][r2*PITCH + s2],     pa + off);
      cpa16(&As[st][r2*PITCH + s2 + 8], pa + off + 8);
    }
    if(BTRANS){
      const hf* pb = seg1 ? pb1t : pb2t;
      cpa16(&Bs[st][br*BP + bc8],       pb + (long)off*N);
      cpa16(&Bs[st][br*BP + bc8 + 8],   pb + (long)off*N + 8);
    } else {
      const hf* pb = seg1 ? pb1n : pb2n;
      cpa16(&Bs[st][r2*PITCH + s2],     pb + off);
      cpa16(&Bs[st][r2*PITCH + s2 + 8], pb + off + 8);
    }
  };

  ld(0); cpa_commit();
  for(int t=0;t<T;t++){
    if(t+1<T){
      ld(t+1); cpa_commit();
      cpa_wait<1>();
    } else {
      cpa_wait<0>();
    }
    __syncthreads();
    int st = t&1;
#pragma unroll
    for(int kk=0;kk<32;kk+=16){
      uint32_t a4[4][4], b2[4][2];
#pragma unroll
      for(int mi=0;mi<4;mi++)
        ldsm4(a4[mi], &As[st][(wm+mi*16+frag_r)*PITCH + kk + frag_k]);
#pragma unroll
      for(int p=0;p<2;p++){
        uint32_t t4[4];
        if(BTRANS){
          ldsm4t(t4, &Bs[st][(kk+frag_r)*BP + wn + p*16 + frag_k]);
          b2[2*p][0]=t4[0]; b2[2*p][1]=t4[1]; b2[2*p+1][0]=t4[2]; b2[2*p+1][1]=t4[3];
        } else {
          ldsm4(t4, &Bs[st][(wn+p*16+frag_r)*PITCH + kk + frag_k]);
          b2[2*p][0]=t4[0]; b2[2*p][1]=t4[2]; b2[2*p+1][0]=t4[1]; b2[2*p+1][1]=t4[3];
        }
      }
#pragma unroll
      for(int mi=0;mi<4;mi++)
#pragma unroll
        for(int ni=0;ni<4;ni++)
          mma_f16(c[mi][ni], a4[mi], b2[ni]);
    }
    __syncthreads();
  }
  // epilogue
#pragma unroll
  for(int mi=0;mi<4;mi++)
#pragma unroll
  for(int ni=0;ni<4;ni++)
#pragma unroll
  for(int hh2=0;hh2<2;hh2++){
    int r = bm + wm + mi*16 + (lane>>2) + hh2*8;
    int cc = bn + wn + ni*8 + (lane&3)*2;
    float v0 = c[mi][ni][hh2*2+0], v1 = c[mi][ni][hh2*2+1];
    if(MODE==M_HOUT){
      *(uint32_t*)&Ch[cbase + (long)r*N + cc] = packh2(v0, v1);
    } else if(MODE==M_RES){
      v0 += bias[cc]   + res[(long)r*N + cc];
      v1 += bias[cc+1] + res[(long)r*N + cc + 1];
      *(float2*)&Cf[cbase + (long)r*N + cc] = make_float2(v0, v1);
    } else if(MODE==M_GELU){
      *(uint32_t*)&Ch[(long)r*N + cc] = packh2(gelu_f(v0 + bias[cc]), gelu_f(v1 + bias[cc+1]));
    } else if(MODE==M_QKV){
      int buf = cc>>10, c10 = cc&1023;
      const float* bp = (buf==0)? bias : (buf==1)? bias2 : bias3;
      int bI = r>>10, l = r&1023, hd = c10>>7, d = c10&127;
      *(uint32_t*)&Ch[(long)buf*SQKV + (((long)(bI*Hh+hd))*Lq + l)*DKc + d]
          = packh2(v0 + bp[c10], v1 + bp[c10+1]);
    } else if(MODE==M_MERGE){
      long bI = z>>3, hd = z&7;
      *(uint32_t*)&Ch[((bI*Lq + r))*Dd + hd*DKc + cc] = packh2(v0, v1);
    } else if(MODE==M_SCORE){
      const float scale = 0.08838834764831845f;
      long bI = z >> 3;
      long rowq = z*((long)Lq*Pp) + (long)r*Pp;
      long rowm = bI*((long)Lq*Lq) + (long)r*Lq;
      long rowa = z*((long)Lq*Lq) + (long)r*Lq;
      int p0 = pm[rowm + cc], p1 = pm[rowm + cc + 1];
      int m0 = msk[rowm + cc], m1 = msk[rowm + cc + 1];
      float s0v = (v0 + __half2float(qrh[rowq + p0]))*scale + res[rowa + cc];
      float s1v = (v1 + __half2float(qrh[rowq + p1]))*scale + res[rowa + cc + 1];
      if(m0==0) s0v = -60000.f;
      if(m1==0) s1v = -60000.f;
      *(uint32_t*)&Ch[cbase + (long)r*N + cc] = packh2(s0v, s1v);
    }
  }
}

// ---------------- LayerNorm -> fp16 ----------------
__global__ void ln_h(const float* __restrict__ x, const float* __restrict__ g,
                     const float* __restrict__ b, hf* __restrict__ y){
  __shared__ float red[256];
  int row = blockIdx.x;
  const float* xr = x + (size_t)row*Dd;
  float v[4]; float s = 0.f;
#pragma unroll
  for(int i=0;i<4;i++){ v[i] = xr[threadIdx.x + i*256]; s += v[i]; }
  red[threadIdx.x] = s; __syncthreads();
  for(int o=128;o>0;o>>=1){ if(threadIdx.x<o) red[threadIdx.x]+=red[threadIdx.x+o]; __syncthreads(); }
  float mean = red[0]*(1.f/Dd); __syncthreads();
  float s2 = 0.f;
#pragma unroll
  for(int i=0;i<4;i++){ float d = v[i]-mean; s2 += d*d; }
  red[threadIdx.x] = s2; __syncthreads();
  for(int o=128;o>0;o>>=1){ if(threadIdx.x<o) red[threadIdx.x]+=red[threadIdx.x+o]; __syncthreads(); }
  float inv = rsqrtf(red[0]*(1.f/Dd) + 1e-6f);
#pragma unroll
  for(int i=0;i<4;i++){
    int cidx = threadIdx.x + i*256;
    y[(long)row*Dd + cidx] = __float2half_rn(g[cidx]*(v[i]-mean)*inv + b[cidx]);
  }
}

// ---------------- weight prep: straight fp32->fp16 converts ----------------
// z: 0..2 = wq|wk|wv -> g_wc[1024][3072] column blocks; 3 = wo flat (1M each)
__global__ void conv_small(const float* __restrict__ wq, const float* __restrict__ wk,
                           const float* __restrict__ wv, const float* __restrict__ wo,
                           hf* __restrict__ wc, hf* __restrict__ woh){
  int z = blockIdx.z;
  int idx = blockIdx.x*256 + threadIdx.x;    // 0..1M-1
  if(z < 3){
    const float* in = (z==0)? wq : (z==1)? wk : wv;
    int r = idx>>10, cidx = idx&1023;
    wc[(long)r*3072 + z*1024 + cidx] = __float2half_rn(in[idx]);
  } else {
    woh[idx] = __float2half_rn(wo[idx]);
  }
}
// z: 0=w1, 1=w2, 2=rk, 3=rv (4M each, flat)
__global__ void conv_big(const float* __restrict__ w1, const float* __restrict__ w2,
                         const float* __restrict__ rk, const float* __restrict__ rv,
                         hf* __restrict__ o1, hf* __restrict__ o2,
                         hf* __restrict__ o3, hf* __restrict__ o4){
  int z = blockIdx.z;
  int idx = blockIdx.x*256 + threadIdx.x;
  const float* in = (z==0)? w1 : (z==1)? w2 : (z==2)? rk : rv;
  hf* o = (z==0)? o1 : (z==1)? o2 : (z==2)? o3 : o4;
  o[idx] = __float2half_rn(in[idx]);
}

// ---------------- fused softmax + scatter (fp16 scores in) ----------------
__global__ void softmax_scatter(const hf* __restrict__ scores, const int* __restrict__ pm,
                                hf* __restrict__ outa, hf* __restrict__ outp){
  __shared__ float red[256];
  __shared__ float sp[Pp];
  int bh = blockIdx.y;
  int b  = bh >> 3;
  int i  = blockIdx.x;
  const hf*  srow = scores + ((size_t)bh*Lq + i)*Lq;
  const int* prow = pm + ((size_t)b*Lq + i)*Lq;
#pragma unroll
  for(int k=0;k<4;k++) sp[threadIdx.x + k*256] = 0.f;
  float v[4]; float mx = -3.0e38f;
#pragma unroll
  for(int k=0;k<4;k++){
    v[k] = __half2float(srow[threadIdx.x + k*256]);
    mx = fmaxf(mx, v[k]);
  }
  red[threadIdx.x] = mx; __syncthreads();
  for(int o=128;o>0;o>>=1){ if(threadIdx.x<o) red[threadIdx.x]=fmaxf(red[threadIdx.x],red[threadIdx.x+o]); __syncthreads(); }
  mx = red[0]; __syncthreads();
  float s = 0.f;
#pragma unroll
  for(int k=0;k<4;k++){ v[k] = expf(v[k]-mx); s += v[k]; }
  red[threadIdx.x] = s; __syncthreads();
  for(int o=128;o>0;o>>=1){ if(threadIdx.x<o) red[threadIdx.x]+=red[threadIdx.x+o]; __syncthreads(); }
  float inv = 1.f/red[0];
  long obase = ((size_t)bh*Lq + i)*Lq;
#pragma unroll
  for(int k=0;k<4;k++){
    int j = threadIdx.x + k*256;
    float a = v[k]*inv;
    outa[obase + j] = __float2half_rn(a);
    atomicAdd(&sp[prow[j]], a);
  }
  __syncthreads();
  long pbase = ((size_t)bh*Lq + i)*Pp;
#pragma unroll
  for(int k=0;k<4;k++){
    int cidx = threadIdx.x + k*256;
    outp[pbase + cidx] = __float2half_rn(sp[cidx]);
  }
}

// ---------------- launch ----------------
extern "C" void kernel_launch(void* const* d_in, const int* in_sizes, int n_in,
                              void* d_out, int out_size){
  const float* content = (const float*)d_in[0];
  const int*   mask    = (const int*)  d_in[1];
  const float* r_k     = (const float*)d_in[2];
  const float* r_v     = (const float*)d_in[3];
  const int*   path_map= (const int*)  d_in[4];
  const float* ap      = (const float*)d_in[5];
  const float* wq = (const float*)d_in[6];  const float* bq = (const float*)d_in[7];
  const float* wk = (const float*)d_in[8];  const float* bk = (const float*)d_in[9];
  const float* wv = (const float*)d_in[10]; const float* bv = (const float*)d_in[11];
  const float* wo = (const float*)d_in[12]; const float* bo = (const float*)d_in[13];
  const float* ln1g = (const float*)d_in[14]; const float* ln1b = (const float*)d_in[15];
  const float* ln2g = (const float*)d_in[16]; const float* ln2b = (const float*)d_in[17];
  const float* w1 = (const float*)d_in[18]; const float* b1 = (const float*)d_in[19];
  const float* w2 = (const float*)d_in[20]; const float* b2 = (const float*)d_in[21];
  float* out = (float*)d_out;

  hf *xn,*qkv,*h,*at,*pt,*wc,*woh,*w1h,*w2h,*rk,*rv,*sc,*qr;
  float *x;
  cudaGetSymbolAddress((void**)&xn, g_xn);
  cudaGetSymbolAddress((void**)&qkv, g_qkv);
  cudaGetSymbolAddress((void**)&h, g_h);
  cudaGetSymbolAddress((void**)&at, g_attn); cudaGetSymbolAddress((void**)&pt, g_path);
  cudaGetSymbolAddress((void**)&wc, g_wc);   cudaGetSymbolAddress((void**)&woh, g_wo);
  cudaGetSymbolAddress((void**)&w1h, g_w1);  cudaGetSymbolAddress((void**)&w2h, g_w2);
  cudaGetSymbolAddress((void**)&rk, g_rk);   cudaGetSymbolAddress((void**)&rv, g_rv);
  cudaGetSymbolAddress((void**)&sc, g_scores);
  cudaGetSymbolAddress((void**)&qr, g_qr);
  cudaGetSymbolAddress((void**)&x, g_x);

  hf* q = qkv;
  hf* k = qkv + SQKV;
  hf* v = qkv + 2*SQKV;
  long sQK = (long)Lq*DKc;

  // prep (2 launches)
  conv_small<<<dim3((Dd*Dd)/256, 1, 4), 256>>>(wq, wk, wv, wo, wc, woh);
  conv_big<<<dim3((Dd*Ff)/256, 1, 4), 256>>>(w1, w2, r_k, r_v, w1h, w2h, rk, rv);

  // LN1
  ln_h<<<Bb*Lq, 256>>>(content, ln1g, ln1b, xn);

  // combined QKV GEMM (B = wc, K-major trans; N=3072)
  hgemm<M_QKV,1><<<dim3(3*Dd/128, (Bb*Lq)/128, 1),256>>>(
      xn, wc, nullptr,nullptr, bq, bk, bv, nullptr, nullptr,nullptr, nullptr,
      nullptr, qkv, 3*Dd, Dd, 0, 0,0,0,0, 0);

  // qr = q@rk^T  (B = rk, N-major; fp16 out)
  hgemm<M_HOUT,0><<<dim3(Pp/128, Lq/128, Bb*Hh),256>>>(
      q, rk, nullptr,nullptr, nullptr,nullptr,nullptr, nullptr, nullptr,nullptr, nullptr,
      nullptr, qr, Pp, DKc, 0, sQK, (long)Pp*DKc, 0,0, (long)Lq*Pp);

  // scores = (q@k^T + gather(qr))*scale + ap, masked (B = k, N-major; fp16 out)
  hgemm<M_SCORE,0><<<dim3(Lq/128, Lq/128, Bb*Hh),256>>>(
      q, k, nullptr,nullptr, nullptr, nullptr,nullptr, ap, path_map, mask, qr,
      nullptr, sc, Lq, DKc, 0, sQK, sQK, 0,0, (long)Lq*Lq);

  // fused softmax + scatter
  softmax_scatter<<<dim3(Lq, Bb*Hh),256>>>(sc, path_map, at, pt);

  // merged: out = attn@v + path@rv (both B K-major natural, trans) -> xn
  hgemm<M_MERGE,1><<<dim3(1, Lq/128, Bb*Hh),256>>>(
      at, v, pt, rv, nullptr,nullptr,nullptr, nullptr, nullptr,nullptr, nullptr,
      nullptr, xn, DKc, Lq, Pp,
      (long)Lq*Lq, sQK, (long)Lq*Pp, (long)Pp*DKc, 0);

  // x = merged@wo + bo + content  (B = wo natural, trans)
  hgemm<M_RES,1><<<dim3(Dd/128,(Bb*Lq)/128,1),256>>>(
      xn, woh, nullptr,nullptr, bo, nullptr,nullptr, content, nullptr,nullptr, nullptr,
      x, nullptr, Dd, Dd, 0, 0,0,0,0, 0);

  // LN2
  ln_h<<<Bb*Lq, 256>>>(x, ln2g, ln2b, xn);

  // h = gelu(xn@w1 + b1)  (B = w1 natural, trans)
  hgemm<M_GELU,1><<<dim3(Ff/128,(Bb*Lq)/128,1),256>>>(
      xn, w1h, nullptr,nullptr, b1, nullptr,nullptr, nullptr, nullptr,nullptr, nullptr,
      nullptr, h, Ff, Dd, 0, 0,0,0,0, 0);

  // out = h@w2 + b2 + x  (B = w2 natural, trans)
  hgemm<M_RES,1><<<dim3(Dd/128,(Bb*Lq)/128,1),256>>>(
      h, w2h, nullptr,nullptr, b2, nullptr,nullptr, x, nullptr,nullptr, nullptr,
      out, nullptr, Dd, Ff, 0, 0,0,0,0, 0);
}